// round 10
// baseline (speedup 1.0000x reference)
#include <cuda_runtime.h>
#include <cuda_bf16.h>
#include <cuda_fp16.h>
#include <math.h>
#include <stdint.h>

// Problem constants (fixed for this dataset)
#define NNODES 50000
#define MAXE   262144
#define DDIM   128
#define HDIM   256
#define NEXP   4

// ---------------- device scratch (static allocation only) ----------------
__device__ int   g_counts[NEXP];
__device__ int   g_flag64;
__device__ int   g_bucket[NEXP][MAXE];      // 4 MB
__device__ float g_topv[MAXE];              // 1 MB
__device__ float g_partial[4096][NEXP];     // per gate-block prob sums
// f16x2-packed W1: word[kpair][col] = (w[2kp][c], w[2kp+1][c]) per expert
__device__ uint32_t g_w1h[131072];

#define OFF2_CAT  0
#define OFF2_DIST 32768
#define OFF2_MUL  49152
#define OFF2_ALL  65536

// ---------------- helpers ----------------
__device__ __forceinline__ void mma_f16(float c[4],
                                        uint32_t a0, uint32_t a1, uint32_t a2, uint32_t a3,
                                        uint32_t b0, uint32_t b1) {
    asm volatile(
        "mma.sync.aligned.m16n8k16.row.col.f32.f16.f16.f32 "
        "{%0,%1,%2,%3}, {%4,%5,%6,%7}, {%8,%9}, {%0,%1,%2,%3};"
        : "+f"(c[0]), "+f"(c[1]), "+f"(c[2]), "+f"(c[3])
        : "r"(a0), "r"(a1), "r"(a2), "r"(a3), "r"(b0), "r"(b1));
}

__device__ __forceinline__ uint32_t packh2(float lo, float hi) {
    const __half2 h = __floats2half2_rn(lo, hi);
    return *reinterpret_cast<const uint32_t*>(&h);
}

// ---------------- kernel 0: init + index dtype sniff ----------------
__global__ void k_init(const void* uptr) {
    if (threadIdx.x < NEXP) g_counts[threadIdx.x] = 0;
    if (threadIdx.x == 0) {
        const int* p = (const int*)uptr;
        int is64 = 1;
        #pragma unroll 1
        for (int i = 0; i < 64; i++) {
            if (p[2 * i + 1] != 0) { is64 = 0; break; }
        }
        g_flag64 = is64;
    }
}

// ---------------- kernel 0b: pack W1 to f16x2 k-pairs ----------------
__global__ __launch_bounds__(256) void k_prep(
    const float* __restrict__ w_cat, const float* __restrict__ w_dist,
    const float* __restrict__ w_mul, const float* __restrict__ w_all)
{
    const int idx = blockIdx.x * 256 + threadIdx.x;   // [0, 131072)
    const float* src;
    int base;
    if (idx < OFF2_DIST)      { src = w_cat;  base = OFF2_CAT;  }
    else if (idx < OFF2_MUL)  { src = w_dist; base = OFF2_DIST; }
    else if (idx < OFF2_ALL)  { src = w_mul;  base = OFF2_MUL;  }
    else                      { src = w_all;  base = OFF2_ALL;  }
    const int r   = idx - base;
    const int k2  = r >> 8;
    const int col = r & 255;
    g_w1h[idx] = packh2(src[k2 * 512 + col], src[k2 * 512 + 256 + col]);
}

// ---------------- kernel 1: gate (r8 version + out zeroing) ----------------
__global__ __launch_bounds__(256) void k_gate(
    const float* __restrict__ z,
    const void*  __restrict__ u_, const void* __restrict__ v_,
    const float* __restrict__ gate_w,   // [512,4] row-major
    const float* __restrict__ gate_b,   // [4]
    float* __restrict__ out,
    int E)
{
    __shared__ __align__(16) float sgw[512 * 4];
    __shared__ float wpart[8][NEXP];
    __shared__ int   sarg[64];
    __shared__ int   srank[64];
    __shared__ int   scnt[NEXP];
    __shared__ int   sbase[NEXP];

    const int tid  = threadIdx.x;
    const int warp = tid >> 5;
    const int lane = tid & 31;

    for (int t = tid; t < 2048; t += 256) sgw[t] = gate_w[t];
    if (tid < NEXP) scnt[tid] = 0;
    __syncthreads();

    const int flag64 = g_flag64;
    const float4* gw4 = reinterpret_cast<const float4*>(sgw);

    float p0 = 0.f, p1 = 0.f, p2 = 0.f, p3 = 0.f;

    const int ebase = (int)blockIdx.x * 64 + warp * 8;
    int uu[8], vv[8];
    #pragma unroll
    for (int t = 0; t < 8; t++) {
        const int e = ebase + t;
        if (e < E) {
            if (flag64) {
                uu[t] = (int)((const long long*)u_)[e];
                vv[t] = (int)((const long long*)v_)[e];
            } else {
                uu[t] = ((const int*)u_)[e];
                vv[t] = ((const int*)v_)[e];
            }
        } else { uu[t] = 0; vv[t] = 0; }
    }

    float za[4], zb[4];
    {
        const float* zu = z + (size_t)uu[0] * DDIM;
        const float* zv = z + (size_t)vv[0] * DDIM;
        #pragma unroll
        for (int kk = 0; kk < 4; kk++) {
            za[kk] = zu[lane + kk * 32];
            zb[kk] = zv[lane + kk * 32];
        }
    }

    #pragma unroll 1
    for (int t = 0; t < 8; t++) {
        const int e = ebase + t;
        if (e >= E) break;

        float ca[4], cb[4];
        #pragma unroll
        for (int kk = 0; kk < 4; kk++) { ca[kk] = za[kk]; cb[kk] = zb[kk]; }

        if (t < 7) {
            const float* zu = z + (size_t)uu[t + 1] * DDIM;
            const float* zv = z + (size_t)vv[t + 1] * DDIM;
            #pragma unroll
            for (int kk = 0; kk < 4; kk++) {
                za[kk] = zu[lane + kk * 32];
                zb[kk] = zv[lane + kk * 32];
            }
        }

        float g0 = 0.f, g1 = 0.f, g2 = 0.f, g3 = 0.f;
        #pragma unroll
        for (int kk = 0; kk < 4; kk++) {
            const int k = lane + kk * 32;
            const float a = ca[kk];
            const float b = cb[kk];
            const float d = fabsf(a - b);
            const float m = a * b;
            const float4 wA = gw4[k];
            const float4 wB = gw4[128 + k];
            const float4 wD = gw4[256 + k];
            const float4 wM = gw4[384 + k];
            g0 += a * wA.x + b * wB.x + d * wD.x + m * wM.x;
            g1 += a * wA.y + b * wB.y + d * wD.y + m * wM.y;
            g2 += a * wA.z + b * wB.z + d * wD.z + m * wM.z;
            g3 += a * wA.w + b * wB.w + d * wD.w + m * wM.w;
        }
        #pragma unroll
        for (int off = 16; off; off >>= 1) {
            g0 += __shfl_xor_sync(0xffffffffu, g0, off);
            g1 += __shfl_xor_sync(0xffffffffu, g1, off);
            g2 += __shfl_xor_sync(0xffffffffu, g2, off);
            g3 += __shfl_xor_sync(0xffffffffu, g3, off);
        }

        if (lane == 0) {
            float l[NEXP];
            l[0] = g0 + gate_b[0]; l[1] = g1 + gate_b[1];
            l[2] = g2 + gate_b[2]; l[3] = g3 + gate_b[3];
            float mx = l[0];
            #pragma unroll
            for (int j = 1; j < NEXP; j++) mx = fmaxf(mx, l[j]);
            float ex[NEXP]; float s = 0.f;
            #pragma unroll
            for (int j = 0; j < NEXP; j++) { ex[j] = expf(l[j] - mx); s += ex[j]; }
            const float inv = 1.f / s;
            float pr[NEXP];
            #pragma unroll
            for (int j = 0; j < NEXP; j++) pr[j] = ex[j] * inv;
            int arg = 0; float best = pr[0];
            #pragma unroll
            for (int j = 1; j < NEXP; j++) if (pr[j] > best) { best = pr[j]; arg = j; }

            g_topv[e] = best;
            sarg[warp * 8 + t] = arg;

            p0 += pr[0]; p1 += pr[1]; p2 += pr[2]; p3 += pr[3];
        }
    }

    if (lane == 0) {
        wpart[warp][0] = p0; wpart[warp][1] = p1;
        wpart[warp][2] = p2; wpart[warp][3] = p3;
    }
    __syncthreads();

    const int e0 = (int)blockIdx.x * 64 + tid;
    if (tid < 64 && e0 < E) {
        out[e0] = 0.f;                      // zeroed for all-expert atomics
        srank[tid] = atomicAdd(&scnt[sarg[tid]], 1);
    }
    __syncthreads();
    if (tid < NEXP) {
        sbase[tid] = atomicAdd(&g_counts[tid], scnt[tid]);
        float s = 0.f;
        #pragma unroll
        for (int w = 0; w < 8; w++) s += wpart[w][tid];
        g_partial[blockIdx.x][tid] = s;
    }
    __syncthreads();
    if (tid < 64 && e0 < E) {
        const int a = sarg[tid];
        g_bucket[a][sbase[a] + srank[tid]] = e0;
    }
}

// ---------------- kernel 2: expert-specialized CTAs, smem-resident W1 -------
// Grid 148, 512 threads. Groups: cat(37) dist(19) mul(18) allN0(37) allN1(37).
// CTA loads its whole W1 slice to smem ONCE, then loops 128-edge tiles of its
// expert. Per 64-K chunk only X is refilled (double-buffered): no cp.async.
// Warp (of 16) = (wm = warp>>3: 64-edge half) x (wn = warp&7: col group).
// N=256 groups: col group = 32 cols (4 n-tiles). N=128 halves: 16 cols (2).

#define XW    136                      // X stride words (128 edges + 8)
#define XBUF  (32 * XW)                // words per X chunk buffer (32 kpairs)
#define WREG  34816                    // words reserved for resident W
// words: W + 2*X + sb1 + sw2 + red + stv + se + su + sv
#define EXP_SMEM ((WREG + 2 * XBUF + 256 + 256 + 1024 + 128 + 3 * 128) * 4)

__global__ __launch_bounds__(512, 1) void k_experts(
    const float* __restrict__ z,
    const void*  __restrict__ u_, const void* __restrict__ v_,
    const float* __restrict__ cb1, const float* __restrict__ cw2, const float* __restrict__ cb2,
    const float* __restrict__ db1, const float* __restrict__ dw2, const float* __restrict__ db2,
    const float* __restrict__ mb1, const float* __restrict__ mw2, const float* __restrict__ mb2,
    const float* __restrict__ ab1, const float* __restrict__ aw2, const float* __restrict__ ab2,
    float* __restrict__ out)
{
    extern __shared__ __align__(16) uint32_t sm[];
    uint32_t* Wsm = sm;                          // [WREG]
    uint32_t* X0  = sm + WREG;                   // [XBUF]
    uint32_t* X1  = X0 + XBUF;                   // [XBUF]
    float* sb1 = (float*)(X1 + XBUF);            // [256]
    float* sw2 = sb1 + 256;                      // [256]
    float* red = sw2 + 256;                      // [128][8]
    float* stv = red + 1024;                     // [128]
    int*   se  = (int*)(stv + 128);              // [128]
    int*   su  = se + 128;                       // [128]
    int*   sv  = su + 128;                       // [128]

    const int tid  = threadIdx.x;
    const int warp = tid >> 5;
    const int lane = tid & 31;
    const int lq   = lane & 3;
    const int lgr  = lane >> 2;
    const int wm   = warp >> 3;                  // edge half (0/1)
    const int wn   = warp & 7;                   // col group (0..7)
    const int xe   = tid & 127;                  // X-fill edge
    const int xg   = tid >> 7;                   // X-fill 16-dim group (0..3)

    // ---- group decode ----
    const int b = blockIdx.x;
    int ex, gi, gn, KPR, NC, WSTR, hofs, half, woff;
    const float *b1p, *w2p, *b2p;
    if (b < 37)       { ex = 0; gi = b;       gn = 37; KPR = 128; NC = 256; hofs = 0;   half = -1; woff = OFF2_CAT;  b1p = cb1; w2p = cw2; b2p = cb2; }
    else if (b < 56)  { ex = 1; gi = b - 37;  gn = 19; KPR = 64;  NC = 256; hofs = 0;   half = -1; woff = OFF2_DIST; b1p = db1; w2p = dw2; b2p = db2; }
    else if (b < 74)  { ex = 2; gi = b - 56;  gn = 18; KPR = 64;  NC = 256; hofs = 0;   half = -1; woff = OFF2_MUL;  b1p = mb1; w2p = mw2; b2p = mb2; }
    else if (b < 111) { ex = 3; gi = b - 74;  gn = 37; KPR = 256; NC = 128; hofs = 0;   half = 0;  woff = OFF2_ALL;  b1p = ab1; w2p = aw2; b2p = ab2; }
    else              { ex = 3; gi = b - 111; gn = 37; KPR = 256; NC = 128; hofs = 128; half = 1;  woff = OFF2_ALL;  b1p = ab1; w2p = aw2; b2p = ab2; }
    WSTR = (NC == 256) ? 264 : 136;
    const int MODE = ex;
    const int NCH  = KPR >> 5;                   // 64-dim chunks

    // ---- load resident W slice (once) ----
    {
        const int nwords = KPR * NC;
        for (int i = tid * 4; i < nwords; i += 2048) {
            const int r = (NC == 256) ? (i >> 8) : (i >> 7);
            const int c = (NC == 256) ? (i & 255) : (i & 127);
            *reinterpret_cast<uint4*>(Wsm + r * WSTR + c) =
                *reinterpret_cast<const uint4*>(g_w1h + woff + (size_t)r * 256 + hofs + c);
        }
        if (tid < NC) { sb1[tid] = b1p[hofs + tid]; sw2[tid] = w2p[hofs + tid]; }
    }
    const float b2s    = b2p[0];
    const int   flag64 = g_flag64;
    const int   cnt    = g_counts[ex];
    const int   ntiles = (cnt + 127) >> 7;
    __syncthreads();

    for (int tile = gi; tile < ntiles; tile += gn) {
        __syncthreads();   // previous tile epilogue done before smem meta reuse
        const int base = tile * 128;
        const int nE   = min(128, cnt - base);

        if (tid < 128) {
            int e = (tid < nE) ? g_bucket[ex][base + tid] : -1;
            se[tid]  = e;
            stv[tid] = (e >= 0) ? g_topv[e] : 0.f;
            int uu = 0, vv = 0;
            if (e >= 0) {
                if (flag64) {
                    uu = (int)((const long long*)u_)[e];
                    vv = (int)((const long long*)v_)[e];
                } else {
                    uu = ((const int*)u_)[e];
                    vv = ((const int*)v_)[e];
                }
            }
            su[tid] = uu; sv[tid] = vv;
        }
        __syncthreads();

        const float* zu = z + (size_t)su[xe] * DDIM;
        const float* zv = z + (size_t)sv[xe] * DDIM;

        float acc[4][4][4];
        #pragma unroll
        for (int m = 0; m < 4; m++)
            #pragma unroll
            for (int n = 0; n < 4; n++)
                #pragma unroll
                for (int q = 0; q < 4; q++) acc[m][n][q] = 0.f;

        // store one 8-dim half of this thread's edge (4 kpair words)
        auto store_half = [&](uint32_t* bX, int type, int h,
                              const float4& a0, const float4& a1,
                              const float4& b0, const float4& b1) {
            const float av[8] = { a0.x, a0.y, a0.z, a0.w, a1.x, a1.y, a1.z, a1.w };
            const float bv[8] = { b0.x, b0.y, b0.z, b0.w, b1.x, b1.y, b1.z, b1.w };
            float vals[8];
            #pragma unroll
            for (int i = 0; i < 8; i++) {
                if (MODE == 0)      vals[i] = (type == 0) ? av[i] : bv[i];
                else if (MODE == 1) vals[i] = fabsf(av[i] - bv[i]);
                else if (MODE == 2) vals[i] = av[i] * bv[i];
                else {
                    if (type == 0)      vals[i] = av[i];
                    else if (type == 1) vals[i] = bv[i];
                    else if (type == 2) vals[i] = fabsf(av[i] - bv[i]);
                    else                vals[i] = av[i] * bv[i];
                }
            }
            #pragma unroll
            for (int j = 0; j < 4; j++)
                bX[(xg * 8 + h * 4 + j) * XW + xe] = packh2(vals[2 * j], vals[2 * j + 1]);
        };

        // one k16 MMA step, N=256 layout (warp covers 32 cols)
        auto step256 = [&](const uint32_t* cX, const uint32_t* cW, int s) {
            const int kr   = s * 8 + lq;
            const int ncol = wn * 32 + lgr;
            uint32_t bh[4][2];
            #pragma unroll
            for (int n = 0; n < 4; n++) {
                bh[n][0] = cW[kr * 264 + ncol + n * 8];
                bh[n][1] = cW[(kr + 4) * 264 + ncol + n * 8];
            }
            #pragma unroll
            for (int m = 0; m < 4; m++) {
                const int xi = kr * XW + wm * 64 + m * 16 + lgr;
                const uint32_t a0 = cX[xi];
                const uint32_t a1 = cX[xi + 8];
                const uint32_t a2 = cX[xi + 4 * XW];
                const uint32_t a3 = cX[xi + 4 * XW + 8];
                #pragma unroll
                for (int n = 0; n < 4; n++)
                    mma_f16(acc[m][n], a0, a1, a2, a3, bh[n][0], bh[n][1]);
            }
        };
        // one k16 MMA step, N=128 layout (warp covers 16 cols)
        auto step128 = [&](const uint32_t* cX, const uint32_t* cW, int s) {
            const int kr   = s * 8 + lq;
            const int ncol = wn * 16 + lgr;
            uint32_t bh[2][2];
            #pragma unroll
            for (int n = 0; n < 2; n++) {
                bh[n][0] = cW[kr * 136 + ncol + n * 8];
                bh[n][1] = cW[(kr + 4) * 136 + ncol + n * 8];
            }
            #pragma unroll
            for (int m = 0; m < 4; m++) {
                const int xi = kr * XW + wm * 64 + m * 16 + lgr;
                const uint32_t a0 = cX[xi];
                const uint32_t a1 = cX[xi + 8];
                const uint32_t a2 = cX[xi + 4 * XW];
                const uint32_t a3 = cX[xi + 4 * XW + 8];
                #pragma unroll
                for (int n = 0; n < 2; n++)
                    mma_f16(acc[m][n], a0, a1, a2, a3, bh[n][0], bh[n][1]);
            }
        };

        // ---- prologue: fill X0 for chunk 0 ----
        {
            #pragma unroll
            for (int h = 0; h < 2; h++) {
                const int d = xg * 16 + h * 8;
                const float4 a0 = *reinterpret_cast<const float4*>(zu + d);
                const float4 a1 = *reinterpret_cast<const float4*>(zu + d + 4);
                const float4 b0 = *reinterpret_cast<const float4*>(zv + d);
                const float4 b1 = *reinterpret_cast<const float4*>(zv + d + 4);
                store_half(X0, 0, h, a0, a1, b0, b1);
            }
        }
        __syncthreads();

        #pragma unroll 1
        for (int cb = 0; cb < NCH; cb++) {
            uint32_t* cur = (cb & 1) ? X1 : X0;
            uint32_t* nxt = (cb & 1) ? X0 : X1;
            const uint32_t* cW = Wsm + (size_t)(cb * 32) * WSTR;
            const bool more = (cb + 1 < NCH);
            const int kb2   = (cb + 1) * 64;
            const int type  = kb2 >> 7;
            const int inner = kb2 & 127;

            float4 pa0, pa1, pb0, pb1;
            if (more) {                         // LDG half 0 of next chunk
                const int d = inner + xg * 16;
                pa0 = *reinterpret_cast<const float4*>(zu + d);
                pa1 = *reinterpret_cast<const float4*>(zu + d + 4);
                pb0 = *reinterpret_cast<const float4*>(zv + d);
                pb1 = *reinterpret_cast<const float4*>(zv + d + 4);
            }

            if (NC == 256) { step256(cur, cW, 0); step256(cur, cW, 1); }
            else           { step128(cur, cW, 0); step128(cur, cW, 1); }

            if (more) {
                store_half(nxt, type, 0, pa0, pa1, pb0, pb1);
                const int d = inner + xg * 16 + 8;   // LDG half 1
                pa0 = *reinterpret_cast<const float4*>(zu + d);
                pa1 = *reinterpret_cast<const float4*>(zu + d + 4);
                pb0 = *reinterpret_cast<const float4*>(zv + d);
                pb1 = *reinterpret_cast<const float4*>(zv + d + 4);
            }

            if (NC == 256) { step256(cur, cW, 2); step256(cur, cW, 3); }
            else           { step128(cur, cW, 2); step128(cur, cW, 3); }

            if (more) store_half(nxt, type, 1, pa0, pa1, pb0, pb1);

            __syncthreads();
        }

        // ---- epilogue: relu + layer-2 partial dot ----
        const int NT = (NC == 256) ? 4 : 2;
        float ep[4][2];
        #pragma unroll
        for (int m = 0; m < 4; m++) { ep[m][0] = 0.f; ep[m][1] = 0.f; }

        #pragma unroll
        for (int n = 0; n < 4; n++) {
            if (n >= NT) break;
            const int c0 = wn * (NT * 8) + n * 8 + 2 * lq;
            const float bb0 = sb1[c0],     bb1 = sb1[c0 + 1];
            const float ww0 = sw2[c0],     ww1 = sw2[c0 + 1];
            #pragma unroll
            for (int m = 0; m < 4; m++) {
                ep[m][0] += fmaxf(acc[m][n][0] + bb0, 0.f) * ww0
                          + fmaxf(acc[m][n][1] + bb1, 0.f) * ww1;
                ep[m][1] += fmaxf(acc[m][n][2] + bb0, 0.f) * ww0
                          + fmaxf(acc[m][n][3] + bb1, 0.f) * ww1;
            }
        }
        #pragma unroll
        for (int m = 0; m < 4; m++) {
            #pragma unroll
            for (int off = 1; off <= 2; off <<= 1) {
                ep[m][0] += __shfl_xor_sync(0xffffffffu, ep[m][0], off);
                ep[m][1] += __shfl_xor_sync(0xffffffffu, ep[m][1], off);
            }
        }
        if (lq == 0) {
            #pragma unroll
            for (int m = 0; m < 4; m++) {
                red[(wm * 64 + m * 16 + lgr) * 8 + wn]     = ep[m][0];
                red[(wm * 64 + m * 16 + 8 + lgr) * 8 + wn] = ep[m][1];
            }
        }
        __syncthreads();

        if (tid < 128 && se[tid] >= 0) {
            float s = 0.f;
            #pragma unroll
            for (int w = 0; w < 8; w++) s += red[tid * 8 + w];
            if (half < 0)       out[se[tid]] = stv[tid] * (s + b2s);
            else if (half == 0) atomicAdd(&out[se[tid]], stv[tid] * (s + b2s));
            else                atomicAdd(&out[se[tid]], stv[tid] * s);
        }
    }
}

// ---------------- kernel 6: aux loss reduction (deterministic) ----------------
__global__ __launch_bounds__(256) void k_aux(float* out, int out_size, int nblocks, int E)
{
    __shared__ float s[256];
    float acc[NEXP] = {0.f, 0.f, 0.f, 0.f};
    for (int i = threadIdx.x; i < nblocks; i += 256) {
        #pragma unroll
        for (int j = 0; j < NEXP; j++) acc[j] += g_partial[i][j];
    }
    float tot[NEXP];
    #pragma unroll
    for (int j = 0; j < NEXP; j++) {
        s[threadIdx.x] = acc[j];
        __syncthreads();
        for (int st = 128; st; st >>= 1) {
            if (threadIdx.x < st) s[threadIdx.x] += s[threadIdx.x + st];
            __syncthreads();
        }
        tot[j] = s[0];
        __syncthreads();
    }
    if (threadIdx.x == 0 && out_size > E) {
        float aux = 0.f;
        const float invE = 1.f / (float)E;
        #pragma unroll
        for (int j = 0; j < NEXP; j++) {
            const float m = tot[j] * invE;
            aux += m * m;
        }
        out[E] = aux * (float)NEXP;
    }
}

// ---------------- host launcher ----------------
extern "C" void kernel_launch(void* const* d_in, const int* in_sizes, int n_in,
                              void* d_out, int out_size)
{
    const float* z       = (const float*)d_in[0];
    const void*  u       = d_in[1];
    const void*  v       = d_in[2];
    const float* gate_w  = (const float*)d_in[3];
    const float* gate_b  = (const float*)d_in[4];
    const float* cat_w1  = (const float*)d_in[5];
    const float* cat_b1  = (const float*)d_in[6];
    const float* cat_w2  = (const float*)d_in[7];
    const float* cat_b2  = (const float*)d_in[8];
    const float* dist_w1 = (const float*)d_in[9];
    const float* dist_b1 = (const float*)d_in[10];
    const float* dist_w2 = (const float*)d_in[11];
    const float* dist_b2 = (const float*)d_in[12];
    const float* mul_w1  = (const float*)d_in[13];
    const float* mul_b1  = (const float*)d_in[14];
    const float* mul_w2  = (const float*)d_in[15];
    const float* mul_b2  = (const float*)d_in[16];
    const float* all_w1  = (const float*)d_in[17];
    const float* all_b1  = (const float*)d_in[18];
    const float* all_w2  = (const float*)d_in[19];
    const float* all_b2  = (const float*)d_in[20];
    float* out = (float*)d_out;

    const int E = in_sizes[1];                 // 262144
    const int gateBlocks = (E + 63) / 64;      // 4096

    cudaFuncSetAttribute(k_experts, cudaFuncAttributeMaxDynamicSharedMemorySize, EXP_SMEM);

    k_init<<<1, 256>>>(u);
    k_prep<<<512, 256>>>(cat_w1, dist_w1, mul_w1, all_w1);
    k_gate<<<gateBlocks, 256>>>(z, u, v, gate_w, gate_b, out, E);

    k_experts<<<148, 512, EXP_SMEM>>>(z, u, v,
        cat_b1, cat_w2, cat_b2,
        dist_b1, dist_w2, dist_b2,
        mul_b1, mul_w2, mul_b2,
        all_b1, all_w2, all_b2,
        out);

    k_aux<<<1, 256>>>(out, out_size, gateBlocks, E);
}

// round 11
// speedup vs baseline: 1.8886x; 1.8886x over previous
#include <cuda_runtime.h>
#include <cuda_bf16.h>
#include <cuda_fp16.h>
#include <math.h>
#include <stdint.h>

// Problem constants (fixed for this dataset)
#define NNODES 50000
#define MAXE   262144
#define DDIM   128
#define HDIM   256
#define NEXP   4

// ---------------- device scratch (static allocation only) ----------------
__device__ int   g_counts[NEXP];
__device__ int   g_flag64;
__device__ int   g_bucket[NEXP][MAXE];      // 4 MB
__device__ float g_topv[MAXE];              // 1 MB
__device__ float g_partial[4096][NEXP];     // per gate-block prob sums
// f16x2-packed W1 for all experts: word[kpair][col] = (w[2kp][c], w[2kp+1][c])
__device__ uint32_t g_w1h[131072];

#define OFF2_CAT  0
#define OFF2_DIST 32768
#define OFF2_MUL  49152
#define OFF2_ALL  65536

// ---------------- helpers ----------------
__device__ __forceinline__ void mma_f16(float c[4],
                                        uint32_t a0, uint32_t a1, uint32_t a2, uint32_t a3,
                                        uint32_t b0, uint32_t b1) {
    asm volatile(
        "mma.sync.aligned.m16n8k16.row.col.f32.f16.f16.f32 "
        "{%0,%1,%2,%3}, {%4,%5,%6,%7}, {%8,%9}, {%0,%1,%2,%3};"
        : "+f"(c[0]), "+f"(c[1]), "+f"(c[2]), "+f"(c[3])
        : "r"(a0), "r"(a1), "r"(a2), "r"(a3), "r"(b0), "r"(b1));
}

__device__ __forceinline__ uint32_t packh2(float lo, float hi) {
    const __half2 h = __floats2half2_rn(lo, hi);
    return *reinterpret_cast<const uint32_t*>(&h);
}

__device__ __forceinline__ void cp_async16(uint32_t smem_addr, const void* gptr) {
    asm volatile("cp.async.cg.shared.global [%0], [%1], 16;\n"
                 :: "r"(smem_addr), "l"(gptr));
}
__device__ __forceinline__ void cp_async_commit() {
    asm volatile("cp.async.commit_group;\n");
}
__device__ __forceinline__ void cp_async_wait0() {
    asm volatile("cp.async.wait_group 0;\n");
}

// ---------------- kernel 0: pack W1 to f16x2 k-pairs (+init/sniff in blk 0) --
__global__ __launch_bounds__(256) void k_prep(
    const float* __restrict__ w_cat, const float* __restrict__ w_dist,
    const float* __restrict__ w_mul, const float* __restrict__ w_all,
    const void* __restrict__ uptr)
{
    if (blockIdx.x == 0) {
        if (threadIdx.x < NEXP) g_counts[threadIdx.x] = 0;
        if (threadIdx.x == 0) {
            const int* p = (const int*)uptr;
            int is64 = 1;
            #pragma unroll 1
            for (int i = 0; i < 64; i++) {
                if (p[2 * i + 1] != 0) { is64 = 0; break; }
            }
            g_flag64 = is64;
        }
    }
    const int idx = blockIdx.x * 256 + threadIdx.x;   // [0, 131072)
    const float* src;
    int base;
    if (idx < OFF2_DIST)      { src = w_cat;  base = OFF2_CAT;  }
    else if (idx < OFF2_MUL)  { src = w_dist; base = OFF2_DIST; }
    else if (idx < OFF2_ALL)  { src = w_mul;  base = OFF2_MUL;  }
    else                      { src = w_all;  base = OFF2_ALL;  }
    const int r   = idx - base;
    const int k2  = r >> 8;
    const int col = r & 255;
    g_w1h[idx] = packh2(src[k2 * 512 + col], src[k2 * 512 + 256 + col]);
}

// ---------------- kernel 1: gate (register-blocked 4 edges/pass) ----------
// Block = 256 thr, 8 warps, 64 edges. Warp = 8 edges in 2 passes of 4.
// Weights read from smem ONCE per kk per pass (shared by 4 edges) ->
// smem crossbar traffic /4 vs per-edge reads. Per-edge FMA order identical
// to prior rounds -> bit-identical logits/argmax/buckets.
__global__ __launch_bounds__(256) void k_gate(
    const float* __restrict__ z,
    const void*  __restrict__ u_, const void* __restrict__ v_,
    const float* __restrict__ gate_w,   // [512,4] row-major
    const float* __restrict__ gate_b,   // [4]
    int E)
{
    __shared__ __align__(16) float sgw[512 * 4];
    __shared__ float wpart[8][NEXP];
    __shared__ int   sarg[64];
    __shared__ int   srank[64];
    __shared__ int   scnt[NEXP];
    __shared__ int   sbase[NEXP];

    const int tid  = threadIdx.x;
    const int warp = tid >> 5;
    const int lane = tid & 31;

    for (int t = tid; t < 2048; t += 256) sgw[t] = gate_w[t];
    if (tid < NEXP) scnt[tid] = 0;
    __syncthreads();

    const int flag64 = g_flag64;
    const float4* gw4 = reinterpret_cast<const float4*>(sgw);

    const int ebase = (int)blockIdx.x * 64 + warp * 8;
    int uu[8], vv[8];
    #pragma unroll
    for (int t = 0; t < 8; t++) {
        const int e = ebase + t;
        if (e < E) {
            if (flag64) {
                uu[t] = (int)((const long long*)u_)[e];
                vv[t] = (int)((const long long*)v_)[e];
            } else {
                uu[t] = ((const int*)u_)[e];
                vv[t] = ((const int*)v_)[e];
            }
        } else { uu[t] = 0; vv[t] = 0; }
    }

    float p0 = 0.f, p1 = 0.f, p2 = 0.f, p3 = 0.f;   // per-lane prob partials

    #pragma unroll 1
    for (int pass = 0; pass < 2; pass++) {
        // batch-load z for 4 edges (16 LDG.128-equivalents in flight)
        float za[4][4], zb[4][4];
        #pragma unroll
        for (int e = 0; e < 4; e++) {
            const int t = pass * 4 + e;
            const float* zu = z + (size_t)uu[t] * DDIM;
            const float* zv = z + (size_t)vv[t] * DDIM;
            #pragma unroll
            for (int kk = 0; kk < 4; kk++) {
                za[e][kk] = zu[lane + kk * 32];
                zb[e][kk] = zv[lane + kk * 32];
            }
        }

        float g[4][4];
        #pragma unroll
        for (int e = 0; e < 4; e++)
            #pragma unroll
            for (int j = 0; j < 4; j++) g[e][j] = 0.f;

        #pragma unroll
        for (int kk = 0; kk < 4; kk++) {
            const int k = lane + kk * 32;
            const float4 wA = gw4[k];
            const float4 wB = gw4[128 + k];
            const float4 wD = gw4[256 + k];
            const float4 wM = gw4[384 + k];
            #pragma unroll
            for (int e = 0; e < 4; e++) {
                const float a = za[e][kk];
                const float b = zb[e][kk];
                const float d = fabsf(a - b);
                const float m = a * b;
                g[e][0] += a * wA.x + b * wB.x + d * wD.x + m * wM.x;
                g[e][1] += a * wA.y + b * wB.y + d * wD.y + m * wM.y;
                g[e][2] += a * wA.z + b * wB.z + d * wD.z + m * wM.z;
                g[e][3] += a * wA.w + b * wB.w + d * wD.w + m * wM.w;
            }
        }

        // butterfly reduce all 16 values (same order as before per value)
        #pragma unroll
        for (int off = 16; off; off >>= 1) {
            #pragma unroll
            for (int e = 0; e < 4; e++) {
                #pragma unroll
                for (int j = 0; j < 4; j++)
                    g[e][j] += __shfl_xor_sync(0xffffffffu, g[e][j], off);
            }
        }

        // lanes 0..3 handle edge pass*4+lane (4 softmaxes in parallel)
        if (lane < 4) {
            float l[NEXP];
            if (lane == 0)      { l[0] = g[0][0]; l[1] = g[0][1]; l[2] = g[0][2]; l[3] = g[0][3]; }
            else if (lane == 1) { l[0] = g[1][0]; l[1] = g[1][1]; l[2] = g[1][2]; l[3] = g[1][3]; }
            else if (lane == 2) { l[0] = g[2][0]; l[1] = g[2][1]; l[2] = g[2][2]; l[3] = g[2][3]; }
            else                { l[0] = g[3][0]; l[1] = g[3][1]; l[2] = g[3][2]; l[3] = g[3][3]; }

            const int t = pass * 4 + lane;
            const int e = ebase + t;
            if (e < E) {
                #pragma unroll
                for (int j = 0; j < NEXP; j++) l[j] += gate_b[j];
                float mx = l[0];
                #pragma unroll
                for (int j = 1; j < NEXP; j++) mx = fmaxf(mx, l[j]);
                float ex[NEXP]; float s = 0.f;
                #pragma unroll
                for (int j = 0; j < NEXP; j++) { ex[j] = expf(l[j] - mx); s += ex[j]; }
                const float inv = 1.f / s;
                float pr[NEXP];
                #pragma unroll
                for (int j = 0; j < NEXP; j++) pr[j] = ex[j] * inv;
                int arg = 0; float best = pr[0];
                #pragma unroll
                for (int j = 1; j < NEXP; j++) if (pr[j] > best) { best = pr[j]; arg = j; }

                g_topv[e] = best;
                sarg[warp * 8 + t] = arg;
                p0 += pr[0]; p1 += pr[1]; p2 += pr[2]; p3 += pr[3];
            }
        }
    }

    // sum prob partials across lanes (only lanes 0..3 nonzero)
    #pragma unroll
    for (int off = 16; off; off >>= 1) {
        p0 += __shfl_xor_sync(0xffffffffu, p0, off);
        p1 += __shfl_xor_sync(0xffffffffu, p1, off);
        p2 += __shfl_xor_sync(0xffffffffu, p2, off);
        p3 += __shfl_xor_sync(0xffffffffu, p3, off);
    }
    if (lane == 0) {
        wpart[warp][0] = p0; wpart[warp][1] = p1;
        wpart[warp][2] = p2; wpart[warp][3] = p3;
    }
    __syncthreads();

    const int e0 = (int)blockIdx.x * 64 + tid;
    if (tid < 64 && e0 < E) {
        srank[tid] = atomicAdd(&scnt[sarg[tid]], 1);
    }
    __syncthreads();
    if (tid < NEXP) {
        sbase[tid] = atomicAdd(&g_counts[tid], scnt[tid]);
        float s = 0.f;
        #pragma unroll
        for (int w = 0; w < 8; w++) s += wpart[w][tid];
        g_partial[blockIdx.x][tid] = s;
    }
    __syncthreads();
    if (tid < 64 && e0 < E) {
        const int a = sarg[tid];
        g_bucket[a][sbase[a] + srank[tid]] = e0;
    }
}

// ---------------- kernel 2: merged experts (f16 MMA m16n8k16, KC=64) --------
// EXACT round-8 structure (best measured): tile 64 edges x 256 hidden,
// 8 warps, warp = 64 edges x 32 cols, double-buffered KC=64 chunks,
// fill_x before MMA block, cp.async W stream.

#define KC      64
#define KP      32
#define XSTR2   72
#define WSTR2   264
#define BUFSZ   (KP * XSTR2 + KP * WSTR2)   // 10752 words

__global__ __launch_bounds__(256, 2) void k_experts(
    const float* __restrict__ z,
    const void*  __restrict__ u_, const void* __restrict__ v_,
    const float* __restrict__ cb1, const float* __restrict__ cw2, const float* __restrict__ cb2,
    const float* __restrict__ db1, const float* __restrict__ dw2, const float* __restrict__ db2,
    const float* __restrict__ mb1, const float* __restrict__ mw2, const float* __restrict__ mb2,
    const float* __restrict__ ab1, const float* __restrict__ aw2, const float* __restrict__ ab2,
    float* __restrict__ out)
{
    extern __shared__ __align__(16) uint32_t sm[];
    float* sb1 = (float*)(sm + 2 * BUFSZ);   // [256]
    float* sw2 = sb1 + 256;                  // [256]
    float* red = sw2 + 256;                  // [64][8]
    float* stv = red + 512;                  // [64]
    int*   se  = (int*)(stv + 64);           // [64]
    int*   su  = se + 64;                    // [64]
    int*   sv  = su + 64;                    // [64]

    const int tid  = threadIdx.x;
    const int warp = tid >> 5;
    const int lane = tid & 31;
    const int lq   = lane & 3;
    const int lg   = lane >> 2;
    const int xe   = tid & 63;               // X-fill: edge
    const int xg   = tid >> 6;               // X-fill: 16-dim group

    const int flag64 = g_flag64;

    int wr[8], wc[8];
    #pragma unroll
    for (int i = 0; i < 8; i++) {
        const int idx = tid + i * 256;
        wr[i] = idx >> 6;
        wc[i] = (idx & 63) << 2;
    }

    const int c0n = g_counts[0], c1n = g_counts[1], c2n = g_counts[2], c3n = g_counts[3];
    const int nt0 = (c0n + 63) >> 6, nt1 = (c1n + 63) >> 6;
    const int nt2 = (c2n + 63) >> 6, nt3 = (c3n + 63) >> 6;
    const int p1 = nt0, p2 = p1 + nt1, p3 = p2 + nt2, total = p3 + nt3;

    for (int t = blockIdx.x; t < total; t += gridDim.x) {
        int ex, tile, K, cnt, woff;
        const float *b1p, *w2p, *b2p;
        if (t < p1)      { ex = 0; tile = t;      K = 256; cnt = c0n; woff = OFF2_CAT;  b1p = cb1; w2p = cw2; b2p = cb2; }
        else if (t < p2) { ex = 1; tile = t - p1; K = 128; cnt = c1n; woff = OFF2_DIST; b1p = db1; w2p = dw2; b2p = db2; }
        else if (t < p3) { ex = 2; tile = t - p2; K = 128; cnt = c2n; woff = OFF2_MUL;  b1p = mb1; w2p = mw2; b2p = mb2; }
        else             { ex = 3; tile = t - p3; K = 512; cnt = c3n; woff = OFF2_ALL;  b1p = ab1; w2p = aw2; b2p = ab2; }
        const uint32_t* w1 = g_w1h + woff;
        const int NCH  = K >> 6;             // KC=64
        const int MODE = ex;

        __syncthreads();   // smem reuse guard across tiles
        if (tid < 256) { sb1[tid] = b1p[tid]; sw2[tid] = w2p[tid]; }
        const float b2s = b2p[0];

        const int base = tile * 64;
        const int nE   = min(64, cnt - base);

        if (tid < 64) {
            int e = (tid < nE) ? g_bucket[ex][base + tid] : -1;
            se[tid]  = e;
            stv[tid] = (e >= 0) ? g_topv[e] : 0.f;
            int uu = 0, vv = 0;
            if (e >= 0) {
                if (flag64) {
                    uu = (int)((const long long*)u_)[e];
                    vv = (int)((const long long*)v_)[e];
                } else {
                    uu = ((const int*)u_)[e];
                    vv = ((const int*)v_)[e];
                }
            }
            su[tid] = uu; sv[tid] = vv;
        }
        __syncthreads();

        const float* zu = z + (size_t)su[xe] * DDIM;
        const float* zv = z + (size_t)sv[xe] * DDIM;

        float acc[4][4][4];
        #pragma unroll
        for (int m = 0; m < 4; m++)
            #pragma unroll
            for (int n = 0; n < 4; n++)
                #pragma unroll
                for (int q = 0; q < 4; q++) acc[m][n][q] = 0.f;

        // X fill for chunk cb into buffer (two half passes of 8 dims)
        auto fill_x = [&](uint32_t* bX, int kb) {
            const int type  = kb >> 7;
            const int inner = kb & 127;
            #pragma unroll
            for (int h = 0; h < 2; h++) {
                const int d = inner + xg * 16 + h * 8;
                const float4 a0 = *reinterpret_cast<const float4*>(zu + d);
                const float4 a1 = *reinterpret_cast<const float4*>(zu + d + 4);
                const float4 b0 = *reinterpret_cast<const float4*>(zv + d);
                const float4 b1 = *reinterpret_cast<const float4*>(zv + d + 4);
                const float av[8] = { a0.x, a0.y, a0.z, a0.w, a1.x, a1.y, a1.z, a1.w };
                const float bv[8] = { b0.x, b0.y, b0.z, b0.w, b1.x, b1.y, b1.z, b1.w };
                float vals[8];
                #pragma unroll
                for (int i = 0; i < 8; i++) {
                    if (MODE == 0)      vals[i] = (type == 0) ? av[i] : bv[i];
                    else if (MODE == 1) vals[i] = fabsf(av[i] - bv[i]);
                    else if (MODE == 2) vals[i] = av[i] * bv[i];
                    else {
                        if (type == 0)      vals[i] = av[i];
                        else if (type == 1) vals[i] = bv[i];
                        else if (type == 2) vals[i] = fabsf(av[i] - bv[i]);
                        else                vals[i] = av[i] * bv[i];
                    }
                }
                #pragma unroll
                for (int j = 0; j < 4; j++) {
                    bX[(xg * 8 + h * 4 + j) * XSTR2 + xe] = packh2(vals[2 * j], vals[2 * j + 1]);
                }
            }
        };

        // ---- prologue: chunk 0 into buffer 0 ----
        {
            uint32_t* bW = sm + KP * XSTR2;
            #pragma unroll
            for (int i = 0; i < 8; i++) {
                const uint32_t dst = (uint32_t)__cvta_generic_to_shared(bW + wr[i] * WSTR2 + wc[i]);
                cp_async16(dst, w1 + (size_t)wr[i] * 256 + wc[i]);
            }
            cp_async_commit();
            fill_x(sm, 0);
            cp_async_wait0();
        }
        __syncthreads();

        #pragma unroll 1
        for (int cb = 0; cb < NCH; cb++) {
            uint32_t* cur = sm + (cb & 1) * BUFSZ;
            uint32_t* nxt = sm + ((cb + 1) & 1) * BUFSZ;

            const bool more = (cb + 1 < NCH);
            if (more) {
                const int kb2 = (cb + 1) * KC;
                uint32_t* bW = nxt + KP * XSTR2;
                #pragma unroll
                for (int i = 0; i < 8; i++) {
                    const uint32_t dst = (uint32_t)__cvta_generic_to_shared(bW + wr[i] * WSTR2 + wc[i]);
                    cp_async16(dst, w1 + (size_t)(kb2 / 2 + wr[i]) * 256 + wc[i]);
                }
                cp_async_commit();
                fill_x(nxt, kb2);
            }

            const uint32_t* cX = cur;
            const uint32_t* cW = cur + KP * XSTR2;

            #pragma unroll
            for (int s = 0; s < 4; s++) {        // 4 x k16 steps
                const int kr   = s * 8 + lq;
                const int ncol = warp * 32 + lg;

                uint32_t bh[4][2];
                #pragma unroll
                for (int n = 0; n < 4; n++) {
                    bh[n][0] = cW[kr * WSTR2 + ncol + n * 8];
                    bh[n][1] = cW[(kr + 4) * WSTR2 + ncol + n * 8];
                }

                #pragma unroll
                for (int m = 0; m < 4; m++) {
                    const int xi = kr * XSTR2 + m * 16 + lg;
                    const uint32_t a0 = cX[xi];
                    const uint32_t a1 = cX[xi + 8];
                    const uint32_t a2 = cX[xi + 4 * XSTR2];
                    const uint32_t a3 = cX[xi + 4 * XSTR2 + 8];
                    #pragma unroll
                    for (int n = 0; n < 4; n++)
                        mma_f16(acc[m][n], a0, a1, a2, a3, bh[n][0], bh[n][1]);
                }
            }

            cp_async_wait0();
            __syncthreads();
        }

        // ---- epilogue: relu + layer-2 dot, reduce ----
        float ep[4][2];
        #pragma unroll
        for (int m = 0; m < 4; m++) { ep[m][0] = 0.f; ep[m][1] = 0.f; }

        #pragma unroll
        for (int n = 0; n < 4; n++) {
            const int c0 = warp * 32 + n * 8 + 2 * lq;
            const float bb0 = sb1[c0],     bb1 = sb1[c0 + 1];
            const float ww0 = sw2[c0],     ww1 = sw2[c0 + 1];
            #pragma unroll
            for (int m = 0; m < 4; m++) {
                ep[m][0] += fmaxf(acc[m][n][0] + bb0, 0.f) * ww0
                          + fmaxf(acc[m][n][1] + bb1, 0.f) * ww1;
                ep[m][1] += fmaxf(acc[m][n][2] + bb0, 0.f) * ww0
                          + fmaxf(acc[m][n][3] + bb1, 0.f) * ww1;
            }
        }
        #pragma unroll
        for (int m = 0; m < 4; m++) {
            #pragma unroll
            for (int off = 1; off <= 2; off <<= 1) {
                ep[m][0] += __shfl_xor_sync(0xffffffffu, ep[m][0], off);
                ep[m][1] += __shfl_xor_sync(0xffffffffu, ep[m][1], off);
            }
        }
        if (lq == 0) {
            #pragma unroll
            for (int m = 0; m < 4; m++) {
                red[(m * 16 + lg) * 8 + warp]     = ep[m][0];
                red[(m * 16 + lg + 8) * 8 + warp] = ep[m][1];
            }
        }
        __syncthreads();

        if (tid < 64 && se[tid] >= 0) {
            float s = 0.f;
            #pragma unroll
            for (int w = 0; w < 8; w++) s += red[tid * 8 + w];
            out[se[tid]] = stv[tid] * (s + b2s);
        }
    }
}

// ---------------- kernel 6: aux loss reduction (deterministic) ----------------
__global__ __launch_bounds__(256) void k_aux(float* out, int out_size, int nblocks, int E)
{
    __shared__ float s[256];
    float acc[NEXP] = {0.f, 0.f, 0.f, 0.f};
    for (int i = threadIdx.x; i < nblocks; i += 256) {
        #pragma unroll
        for (int j = 0; j < NEXP; j++) acc[j] += g_partial[i][j];
    }
    float tot[NEXP];
    #pragma unroll
    for (int j = 0; j < NEXP; j++) {
        s[threadIdx.x] = acc[j];
        __syncthreads();
        for (int st = 128; st; st >>= 1) {
            if (threadIdx.x < st) s[threadIdx.x] += s[threadIdx.x + st];
            __syncthreads();
        }
        tot[j] = s[0];
        __syncthreads();
    }
    if (threadIdx.x == 0 && out_size > E) {
        float aux = 0.f;
        const float invE = 1.f / (float)E;
        #pragma unroll
        for (int j = 0; j < NEXP; j++) {
            const float m = tot[j] * invE;
            aux += m * m;
        }
        out[E] = aux * (float)NEXP;
    }
}

// ---------------- host launcher ----------------
#define EXP_SMEM ((2 * BUFSZ + 256 + 256 + 512 + 64 + 192) * 4)

extern "C" void kernel_launch(void* const* d_in, const int* in_sizes, int n_in,
                              void* d_out, int out_size)
{
    const float* z       = (const float*)d_in[0];
    const void*  u       = d_in[1];
    const void*  v       = d_in[2];
    const float* gate_w  = (const float*)d_in[3];
    const float* gate_b  = (const float*)d_in[4];
    const float* cat_w1  = (const float*)d_in[5];
    const float* cat_b1  = (const float*)d_in[6];
    const float* cat_w2  = (const float*)d_in[7];
    const float* cat_b2  = (const float*)d_in[8];
    const float* dist_w1 = (const float*)d_in[9];
    const float* dist_b1 = (const float*)d_in[10];
    const float* dist_w2 = (const float*)d_in[11];
    const float* dist_b2 = (const float*)d_in[12];
    const float* mul_w1  = (const float*)d_in[13];
    const float* mul_b1  = (const float*)d_in[14];
    const float* mul_w2  = (const float*)d_in[15];
    const float* mul_b2  = (const float*)d_in[16];
    const float* all_w1  = (const float*)d_in[17];
    const float* all_b1  = (const float*)d_in[18];
    const float* all_w2  = (const float*)d_in[19];
    const float* all_b2  = (const float*)d_in[20];
    float* out = (float*)d_out;

    const int E = in_sizes[1];                 // 262144
    const int gateBlocks = (E + 63) / 64;      // 4096

    cudaFuncSetAttribute(k_experts, cudaFuncAttributeMaxDynamicSharedMemorySize, EXP_SMEM);

    k_prep<<<512, 256>>>(cat_w1, dist_w1, mul_w1, all_w1, u);
    k_gate<<<gateBlocks, 256>>>(z, u, v, gate_w, gate_b, E);

    k_experts<<<2048, 256, EXP_SMEM>>>(z, u, v,
        cat_b1, cat_w2, cat_b2,
        dist_b1, dist_w2, dist_b2,
        mul_b1, mul_w2, mul_b2,
        all_b1, all_w2, all_b2,
        out);

    k_aux<<<1, 256>>>(out, out_size, gateBlocks, E);
}